// round 8
// baseline (speedup 1.0000x reference)
#include <cuda_runtime.h>
#include <math.h>

#define HWPX 16384      // 128*128
#define NIMG 2048       // 128 bg * 16 c
#define NBG  128
#define EPSF 1e-5f

// ---------------- scratch (static __device__, no allocations) ----------------
__device__ float  d_hw[NIMG * 256];    // [img][l]: l<128 row means, l>=128 col means
__device__ float  d_s1[NIMG * 256];    // silu(hw1)
__device__ float  d_s2[NIMG * 256];    // silu(hw2)
__device__ float4 d_stats[NIMG];       // (S1, Q1, S2, Q2)

__device__ __forceinline__ float siluf(float v) { return v / (1.0f + __expf(-v)); }

// ================= K1: per-image row means + col means =================
// grid 2048 x 256, reverse img order so K1's tail is K2's head in L2.
__global__ __launch_bounds__(256) void k1_means(const float* __restrict__ x) {
    const int img = 2047 - blockIdx.x;
    const float* g = x + (size_t)img * HWPX;
    const int lane = threadIdx.x & 31, w = threadIdx.x >> 5;   // 8 warps
    __shared__ float colp[8][128];

    float4 cs = make_float4(0.f, 0.f, 0.f, 0.f);
    #pragma unroll
    for (int k = 0; k < 16; k += 4) {
        float4 v[4]; float r[4];
        #pragma unroll
        for (int t = 0; t < 4; t++)
            v[t] = __ldg((const float4*)(g + (w + 8 * (k + t)) * 128) + lane);
        #pragma unroll
        for (int t = 0; t < 4; t++) {
            cs.x += v[t].x; cs.y += v[t].y; cs.z += v[t].z; cs.w += v[t].w;
            r[t] = (v[t].x + v[t].y) + (v[t].z + v[t].w);
        }
        #pragma unroll
        for (int off = 16; off; off >>= 1) {
            #pragma unroll
            for (int t = 0; t < 4; t++) r[t] += __shfl_down_sync(0xffffffffu, r[t], off);
        }
        if (lane == 0) {
            #pragma unroll
            for (int t = 0; t < 4; t++)
                d_hw[img * 256 + (w + 8 * (k + t))] = r[t] * (1.f / 128.f);
        }
    }
    colp[w][4 * lane + 0] = cs.x;
    colp[w][4 * lane + 1] = cs.y;
    colp[w][4 * lane + 2] = cs.z;
    colp[w][4 * lane + 3] = cs.w;
    __syncthreads();
    if (threadIdx.x < 128) {
        float s = 0.f;
        #pragma unroll
        for (int ww = 0; ww < 8; ww++) s += colp[ww][threadIdx.x];
        d_hw[img * 256 + 128 + threadIdx.x] = s * (1.f / 128.f);
    }
}

// ================= K2: fused kA-mix (own channel) + separable moment sums =================
// grid 2048 x 256, ascending img order.
__global__ __launch_bounds__(256) void k2_mix_stats(const float* __restrict__ x,
                                                    const float* __restrict__ w1, const float* __restrict__ b1,
                                                    const float* __restrict__ w3, const float* __restrict__ b3) {
    const int img = blockIdx.x;
    const int bg = img >> 4, c = img & 15;
    const int lane = threadIdx.x & 31, w = threadIdx.x >> 5;

    __shared__ float hw[16][258];                 // means of all 16 channels + halo
    __shared__ __align__(16) float st1[256], st2[256];
    __shared__ float hq1[128], hq2[128];
    __shared__ float red[8][4];

    // load the group's means (L2-hot from K1)
    #pragma unroll
    for (int ic = 0; ic < 16; ic++)
        hw[ic][threadIdx.x + 1] = __ldg(&d_hw[(bg * 16 + ic) * 256 + threadIdx.x]);
    if (threadIdx.x < 16) { hw[threadIdx.x][0] = 0.f; hw[threadIdx.x][257] = 0.f; }
    __syncthreads();

    // recompute kA mix for o = c only (trivial redundant compute)
    {
        const int l = threadIdx.x;
        float a1 = __ldg(b1 + c), a2 = __ldg(b3 + c);
        #pragma unroll
        for (int i = 0; i < 16; i++) {
            const float h0 = hw[i][l], h1 = hw[i][l + 1], h2 = hw[i][l + 2];
            a1 = fmaf(__ldg(w1 + c * 16 + i), h1, a1);
            const int wb = (c * 16 + i) * 9;          // w3[o][i][kh][kw], center kw=1
            a2 = fmaf(__ldg(w3 + wb + 1), h0,
                 fmaf(__ldg(w3 + wb + 4), h1,
                 fmaf(__ldg(w3 + wb + 7), h2, a2)));
        }
        const float s1v = siluf(a1), s2v = siluf(a2);
        st1[l] = s1v; st2[l] = s2v;
        d_s1[img * 256 + l] = s1v;                    // for K3
        d_s2[img * 256 + l] = s2v;
        if (l < 128) { hq1[l] = s1v * s1v; hq2[l] = s2v * s2v; }
    }
    __syncthreads();

    // separable moment sums over x
    const float* g = x + (size_t)img * HWPX;
    const float4 wa = *(const float4*)&st1[128 + 4 * lane];
    const float4 wb = *(const float4*)&st2[128 + 4 * lane];
    float4 wa2, wb2;
    wa2.x = wa.x * wa.x; wa2.y = wa.y * wa.y; wa2.z = wa.z * wa.z; wa2.w = wa.w * wa.w;
    wb2.x = wb.x * wb.x; wb2.y = wb.y * wb.y; wb2.z = wb.z * wb.z; wb2.w = wb.w * wb.w;

    float sa = 0.f, qa = 0.f, sb = 0.f, qb = 0.f;
    #pragma unroll
    for (int k = 0; k < 16; k += 4) {
        float4 v[4];
        #pragma unroll
        for (int t = 0; t < 4; t++)
            v[t] = __ldg((const float4*)(g + (w + 8 * (k + t)) * 128) + lane);
        #pragma unroll
        for (int t = 0; t < 4; t++) {
            const int i = w + 8 * (k + t);
            const float h1 = st1[i], h2 = st2[i];
            const float h1q = hq1[i], h2q = hq2[i];
            const float v2x = v[t].x * v[t].x, v2y = v[t].y * v[t].y;
            const float v2z = v[t].z * v[t].z, v2w = v[t].w * v[t].w;
            float d1 = v[t].x * wa.x;
            d1 = fmaf(v[t].y, wa.y, d1); d1 = fmaf(v[t].z, wa.z, d1); d1 = fmaf(v[t].w, wa.w, d1);
            float e1 = v2x * wa2.x;
            e1 = fmaf(v2y, wa2.y, e1); e1 = fmaf(v2z, wa2.z, e1); e1 = fmaf(v2w, wa2.w, e1);
            sa = fmaf(h1, d1, sa);
            qa = fmaf(h1q, e1, qa);
            float d2 = v[t].x * wb.x;
            d2 = fmaf(v[t].y, wb.y, d2); d2 = fmaf(v[t].z, wb.z, d2); d2 = fmaf(v[t].w, wb.w, d2);
            float e2 = v2x * wb2.x;
            e2 = fmaf(v2y, wb2.y, e2); e2 = fmaf(v2z, wb2.z, e2); e2 = fmaf(v2w, wb2.w, e2);
            sb = fmaf(h2, d2, sb);
            qb = fmaf(h2q, e2, qb);
        }
    }
    #pragma unroll
    for (int off = 16; off; off >>= 1) {
        sa += __shfl_down_sync(0xffffffffu, sa, off);
        qa += __shfl_down_sync(0xffffffffu, qa, off);
        sb += __shfl_down_sync(0xffffffffu, sb, off);
        qb += __shfl_down_sync(0xffffffffu, qb, off);
    }
    if (lane == 0) { red[w][0] = sa; red[w][1] = qa; red[w][2] = sb; red[w][3] = qb; }
    __syncthreads();
    if (threadIdx.x == 0) {
        float4 st = make_float4(0.f, 0.f, 0.f, 0.f);
        #pragma unroll
        for (int ww = 0; ww < 8; ww++) {
            st.x += red[ww][0]; st.y += red[ww][1];
            st.z += red[ww][2]; st.w += red[ww][3];
        }
        d_stats[img] = st;
    }
}

// ================= K3: fused kB scalars + wts + gate + output =================
// grid (16 slabs, 128 bg) x 256, reverse bg order (handoff from K2's tail).
__global__ __launch_bounds__(256) void k3_out(const float* __restrict__ x, float* __restrict__ out,
                                              const float* __restrict__ gnw, const float* __restrict__ gnb) {
    const int bg = 127 - blockIdx.y;
    const int i0 = blockIdx.x * 8;
    const int lane = threadIdx.x & 31, w = threadIdx.x >> 5;   // warp w -> row i0+w

    __shared__ __align__(16) float j1[16][128], j2[16][128];
    __shared__ float th1[16][8], th2[16][8];
    __shared__ float k1s[16], k2s[16];
    __shared__ float Cs;

    for (int idx = threadIdx.x; idx < 2048; idx += 256) {
        const int c = idx >> 7, j = idx & 127;
        j1[c][j] = __ldg(&d_s1[(bg * 16 + c) * 256 + 128 + j]);
        j2[c][j] = __ldg(&d_s2[(bg * 16 + c) * 256 + 128 + j]);
    }
    if (threadIdx.x < 128) {
        const int c = threadIdx.x >> 3, r = threadIdx.x & 7;
        th1[c][r] = __ldg(&d_s1[(bg * 16 + c) * 256 + i0 + r]);
        th2[c][r] = __ldg(&d_s2[(bg * 16 + c) * 256 + i0 + r]);
    }
    __syncthreads();

    // recompute kB scalars in warp 0 (trivial redundant compute)
    if (threadIdx.x < 32) {
        const int c = lane;
        const float gb = (c < 16) ? __ldg(gnb + c) : -1e30f;
        float m = gb;
        #pragma unroll
        for (int off = 8; off; off >>= 1) m = fmaxf(m, __shfl_xor_sync(0xffffffffu, m, off, 16));
        const float e = (c < 16) ? __expf(gb - m) : 0.f;
        float se = e;
        #pragma unroll
        for (int off = 8; off; off >>= 1) se += __shfl_xor_sync(0xffffffffu, se, off, 16);
        float part = 0.f;
        if (c < 16) {
            const float a = e / se;                  // a1 == a2 == softmax(gn_b)
            const float4 st = d_stats[bg * 16 + c];
            const float mu1 = st.x * (1.f / 16384.f);
            const float r1  = rsqrtf(st.y * (1.f / 16384.f) - mu1 * mu1 + EPSF);
            const float mu2 = st.z * (1.f / 16384.f);
            const float r2  = rsqrtf(st.w * (1.f / 16384.f) - mu2 * mu2 + EPSF);
            const float gw = __ldg(gnw + c);
            k1s[c] = a * gw * r1;
            k2s[c] = a * gw * r2;
            part = a * (2.f * gb - gw * (mu1 * r1 + mu2 * r2));
        }
        #pragma unroll
        for (int off = 16; off; off >>= 1) part += __shfl_down_sync(0xffffffffu, part, off);
        if (lane == 0) Cs = part;
    }
    __syncthreads();
    if (threadIdx.x < 128) {
        const int c = threadIdx.x >> 3, r = threadIdx.x & 7;
        th1[c][r] *= k1s[c];
        th2[c][r] *= k2s[c];
    }
    __syncthreads();

    const float* xb = x   + (size_t)bg * 16 * HWPX;
    float*       ob = out + (size_t)bg * 16 * HWPX;
    const int row = i0 + w;
    const float Cc = Cs;

    float4 v[16];
    float4 acc = make_float4(Cc, Cc, Cc, Cc);
    #pragma unroll
    for (int c = 0; c < 16; c++) {
        v[c] = __ldcs((const float4*)(xb + c * HWPX + row * 128) + lane);
        const float a1 = th1[c][w], a2 = th2[c][w];
        const float4 ja = *(const float4*)&j1[c][4 * lane];
        const float4 jb = *(const float4*)&j2[c][4 * lane];
        acc.x += v[c].x * fmaf(a1, ja.x, a2 * jb.x);
        acc.y += v[c].y * fmaf(a1, ja.y, a2 * jb.y);
        acc.z += v[c].z * fmaf(a1, ja.z, a2 * jb.z);
        acc.w += v[c].w * fmaf(a1, ja.w, a2 * jb.w);
    }
    float4 sw;
    sw.x = siluf(acc.x); sw.y = siluf(acc.y); sw.z = siluf(acc.z); sw.w = siluf(acc.w);
    #pragma unroll
    for (int c = 0; c < 16; c++) {
        float4 o;
        o.x = v[c].x * sw.x; o.y = v[c].y * sw.y;
        o.z = v[c].z * sw.z; o.w = v[c].w * sw.w;
        __stcs((float4*)(ob + c * HWPX + row * 128) + lane, o);
    }
}

// ---------------- launch ----------------
extern "C" void kernel_launch(void* const* d_in, const int* in_sizes, int n_in,
                              void* d_out, int out_size) {
    const float* x    = (const float*)d_in[0];
    const float* w1   = (const float*)d_in[1];
    const float* b1   = (const float*)d_in[2];
    const float* w3   = (const float*)d_in[3];
    const float* b3   = (const float*)d_in[4];
    const float* gn_w = (const float*)d_in[5];
    const float* gn_b = (const float*)d_in[6];
    float* out = (float*)d_out;

    k1_means<<<2048, 256>>>(x);
    k2_mix_stats<<<2048, 256>>>(x, w1, b1, w3, b3);
    k3_out<<<dim3(16, 128), 256>>>(x, out, gn_w, gn_b);
}

// round 9
// speedup vs baseline: 1.2600x; 1.2600x over previous
#include <cuda_runtime.h>
#include <math.h>
#include <stdint.h>

#define HWPX 16384        // 128*128 floats per image
#define CHUNK_BYTES 65536 // one channel image (128*128*4)
#define EPSF 1e-5f

__device__ __forceinline__ float siluf(float v) { return v / (1.0f + __expf(-v)); }

__device__ __forceinline__ uint32_t smem_u32(const void* p) {
    uint32_t a;
    asm("{ .reg .u64 t; cvta.to.shared.u64 t, %1; cvt.u32.u64 %0, t; }" : "=r"(a) : "l"(p));
    return a;
}
__device__ __forceinline__ void mbar_init(uint32_t a, uint32_t count) {
    asm volatile("mbarrier.init.shared.b64 [%0], %1;" :: "r"(a), "r"(count) : "memory");
}
__device__ __forceinline__ void mbar_expect_tx(uint32_t a, uint32_t bytes) {
    asm volatile("mbarrier.arrive.expect_tx.shared.b64 _, [%0], %1;" :: "r"(a), "r"(bytes) : "memory");
}
__device__ __forceinline__ void mbar_wait(uint32_t a, uint32_t parity) {
    asm volatile(
        "{\n\t.reg .pred P;\n\t"
        "WAIT_%=:\n\t"
        "mbarrier.try_wait.parity.acquire.cta.shared::cta.b64 P, [%0], %1, 0x989680;\n\t"
        "@!P bra WAIT_%=;\n\t"
        "}" :: "r"(a), "r"(parity) : "memory");
}
__device__ __forceinline__ void bulk_load(uint32_t dst, const void* src, uint32_t bytes, uint32_t mbar) {
    asm volatile(
        "cp.async.bulk.shared::cluster.global.mbarrier::complete_tx::bytes [%0], [%1], %2, [%3];"
        :: "r"(dst), "l"(src), "r"(bytes), "r"(mbar) : "memory");
}

// One block per bg-group, 512 threads. TMA-pipelined P1/P2 streaming through
// a 2x64KB smem double buffer; kA/kB smem-only; C = LDG(L2-hot) + streaming stores.
__global__ __launch_bounds__(512, 1)
void mega(const float* __restrict__ x,
          const float* __restrict__ w1, const float* __restrict__ b1,
          const float* __restrict__ w3, const float* __restrict__ b3,
          const float* __restrict__ gnw, const float* __restrict__ gnb,
          float* __restrict__ out)
{
    extern __shared__ float sm[];
    float* stage = sm;                 // 2 x 16384 floats (2 x 64 KB)
    float* s1    = sm + 32768;         // [16][256]
    float* s2    = sm + 36864;         // [16][256]
    float* hwb   = sm + 40960;         // [16][258]; aliased by sq tables after kA
    float* sq1   = hwb;                // [16][128]
    float* sq2   = hwb + 2048;         // [16][128]
    float* colp  = sm + 45088;         // [16][128] per-warp column partials

    __shared__ __align__(8) uint64_t mbar_store[2];
    __shared__ float w1s[256], w3s[768], b1s[16], b3s[16], gbsh[16];
    __shared__ float statv[64], k1s[16], k2s[16], cpart[16];
    __shared__ float red[16][4];
    __shared__ float Csm;

    const int bg   = blockIdx.x;
    const int tid  = threadIdx.x;
    const int lane = tid & 31;
    const int w    = tid >> 5;                    // 0..15
    const float* xb = x   + (size_t)bg * 16 * HWPX;
    float*       ob = out + (size_t)bg * 16 * HWPX;

    const uint32_t mb0 = smem_u32(&mbar_store[0]);
    const uint32_t mb1 = smem_u32(&mbar_store[1]);
    const uint32_t st0 = smem_u32(stage);
    const uint32_t st1 = smem_u32(stage + 16384);

    // ---- stage tiny weights ----
    if (tid < 256) w1s[tid] = __ldg(w1 + tid);
    for (int i2 = tid; i2 < 768; i2 += 512) w3s[i2] = __ldg(w3 + i2 * 3 + 1); // kw=1 column
    if (tid < 16) { b1s[tid] = __ldg(b1 + tid); b3s[tid] = __ldg(b3 + tid); gbsh[tid] = __ldg(gnb + tid); }

    if (tid == 0) { mbar_init(mb0, 1); mbar_init(mb1, 1); }
    __syncthreads();

    // ================= P1: row + col means via TMA pipeline =================
    if (tid == 0) {
        mbar_expect_tx(mb0, CHUNK_BYTES);
        bulk_load(st0, xb, CHUNK_BYTES, mb0);
    }
    #pragma unroll 1
    for (int c = 0; c < 16; c++) {
        const int buf = c & 1;
        mbar_wait(buf ? mb1 : mb0, (c >> 1) & 1);
        const float* S = stage + buf * 16384;

        float4 ca = make_float4(0.f, 0.f, 0.f, 0.f);
        float rs[8];
        #pragma unroll
        for (int r = 0; r < 8; r++) {
            const float4 v = *(const float4*)(S + (w * 8 + r) * 128 + 4 * lane);
            ca.x += v.x; ca.y += v.y; ca.z += v.z; ca.w += v.w;
            rs[r] = (v.x + v.y) + (v.z + v.w);
        }
        #pragma unroll
        for (int off = 16; off; off >>= 1) {
            #pragma unroll
            for (int r = 0; r < 8; r++) rs[r] += __shfl_down_sync(0xffffffffu, rs[r], off);
        }
        if (lane == 0) {
            #pragma unroll
            for (int r = 0; r < 8; r++) hwb[c * 258 + 1 + w * 8 + r] = rs[r] * (1.f / 128.f);
        }
        *(float4*)(colp + w * 128 + 4 * lane) = ca;
        __syncthreads();                              // chunk consumed; colp ready

        if (tid == 0 && c < 15) {                     // prefetch chunk c+1 into other buffer
            const uint32_t mbn = (buf ^ 1) ? mb1 : mb0;
            mbar_expect_tx(mbn, CHUNK_BYTES);
            bulk_load((buf ^ 1) ? st1 : st0, xb + (size_t)(c + 1) * HWPX, CHUNK_BYTES, mbn);
        }
        if (tid < 128) {                              // fold 16 warps' column partials
            float s = 0.f;
            #pragma unroll
            for (int ww = 0; ww < 16; ww++) s += colp[ww * 128 + tid];
            hwb[c * 258 + 129 + tid] = s * (1.f / 128.f);
        }
        __syncthreads();                              // colp reusable next chunk
    }

    // prefetch P2 chunks 0 and 1 (buffers free; overlaps kA)
    if (tid == 0) {
        mbar_expect_tx(mb0, CHUNK_BYTES);
        bulk_load(st0, xb, CHUNK_BYTES, mb0);
        mbar_expect_tx(mb1, CHUNK_BYTES);
        bulk_load(st1, xb + HWPX, CHUNK_BYTES, mb1);
    }
    if (tid < 16) { hwb[tid * 258] = 0.f; hwb[tid * 258 + 257] = 0.f; }   // conv halo
    __syncthreads();

    // ================= kA: channel mix over concat length 256 =================
    for (int idx = tid; idx < 4096; idx += 512) {
        const int o = idx >> 8, l = idx & 255;
        float a1 = b1s[o], a2 = b3s[o];
        #pragma unroll
        for (int i = 0; i < 16; i++) {
            const float* h = hwb + i * 258 + l;
            const float h0 = h[0], h1 = h[1], h2 = h[2];
            a1 = fmaf(w1s[o * 16 + i], h1, a1);
            const int wb = (o * 16 + i) * 3;
            a2 = fmaf(w3s[wb], h0, fmaf(w3s[wb + 1], h1, fmaf(w3s[wb + 2], h2, a2)));
        }
        s1[o * 256 + l] = siluf(a1);
        s2[o * 256 + l] = siluf(a2);
    }
    __syncthreads();
    // h^2 tables into the (now dead) hwb region
    for (int idx = tid; idx < 2048; idx += 512) {
        const int c = idx >> 7, i = idx & 127;
        const float a = s1[c * 256 + i];
        const float b = s2[c * 256 + i];
        sq1[idx] = a * a;
        sq2[idx] = b * b;
    }
    __syncthreads();

    // ================= P2: separable moment sums via TMA pipeline =================
    #pragma unroll 1
    for (int c = 0; c < 16; c++) {
        const int buf = c & 1;
        mbar_wait(buf ? mb1 : mb0, (c >> 1) & 1);     // parity continues from P1 (8 even uses)
        const float* S = stage + buf * 16384;

        const float4 wa = *(const float4*)(s1 + c * 256 + 128 + 4 * lane);
        const float4 wb = *(const float4*)(s2 + c * 256 + 128 + 4 * lane);
        float4 wa2, wb2;
        wa2.x = wa.x * wa.x; wa2.y = wa.y * wa.y; wa2.z = wa.z * wa.z; wa2.w = wa.w * wa.w;
        wb2.x = wb.x * wb.x; wb2.y = wb.y * wb.y; wb2.z = wb.z * wb.z; wb2.w = wb.w * wb.w;

        float sa = 0.f, qa = 0.f, sb = 0.f, qb = 0.f;
        #pragma unroll
        for (int r = 0; r < 8; r++) {
            const int i = w * 8 + r;
            const float4 v = *(const float4*)(S + i * 128 + 4 * lane);
            const float h1 = s1[c * 256 + i], h2 = s2[c * 256 + i];
            const float h1q = sq1[c * 128 + i], h2q = sq2[c * 128 + i];
            const float v2x = v.x * v.x, v2y = v.y * v.y, v2z = v.z * v.z, v2w = v.w * v.w;
            float d1 = v.x * wa.x;
            d1 = fmaf(v.y, wa.y, d1); d1 = fmaf(v.z, wa.z, d1); d1 = fmaf(v.w, wa.w, d1);
            float e1 = v2x * wa2.x;
            e1 = fmaf(v2y, wa2.y, e1); e1 = fmaf(v2z, wa2.z, e1); e1 = fmaf(v2w, wa2.w, e1);
            sa = fmaf(h1, d1, sa);
            qa = fmaf(h1q, e1, qa);
            float d2 = v.x * wb.x;
            d2 = fmaf(v.y, wb.y, d2); d2 = fmaf(v.z, wb.z, d2); d2 = fmaf(v.w, wb.w, d2);
            float e2 = v2x * wb2.x;
            e2 = fmaf(v2y, wb2.y, e2); e2 = fmaf(v2z, wb2.z, e2); e2 = fmaf(v2w, wb2.w, e2);
            sb = fmaf(h2, d2, sb);
            qb = fmaf(h2q, e2, qb);
        }
        #pragma unroll
        for (int off = 16; off; off >>= 1) {
            sa += __shfl_down_sync(0xffffffffu, sa, off);
            qa += __shfl_down_sync(0xffffffffu, qa, off);
            sb += __shfl_down_sync(0xffffffffu, sb, off);
            qb += __shfl_down_sync(0xffffffffu, qb, off);
        }
        if (lane == 0) { red[w][0] = sa; red[w][1] = qa; red[w][2] = sb; red[w][3] = qb; }
        __syncthreads();                               // chunk consumed; red ready

        if (tid == 0 && c + 2 < 16) {                  // prefetch chunk c+2 into this buffer
            const uint32_t mbn = buf ? mb1 : mb0;
            mbar_expect_tx(mbn, CHUNK_BYTES);
            bulk_load(buf ? st1 : st0, xb + (size_t)(c + 2) * HWPX, CHUNK_BYTES, mbn);
        }
        if (tid < 4) {
            float s = 0.f;
            #pragma unroll
            for (int ww = 0; ww < 16; ww++) s += red[ww][tid];
            statv[c * 4 + tid] = s;
        }
        __syncthreads();                               // red reusable next chunk
    }

    // ================= kB: scalars =================
    if (tid < 16) {
        float m = -1e30f;
        #pragma unroll
        for (int i = 0; i < 16; i++) m = fmaxf(m, gbsh[i]);
        float se = 0.f;
        #pragma unroll
        for (int i = 0; i < 16; i++) se += __expf(gbsh[i] - m);
        const float a = __expf(gbsh[tid] - m) / se;    // a1 == a2 == softmax(gn_b)
        const float S1 = statv[tid * 4], Q1 = statv[tid * 4 + 1];
        const float S2 = statv[tid * 4 + 2], Q2 = statv[tid * 4 + 3];
        const float mu1 = S1 * (1.f / 16384.f);
        const float r1  = rsqrtf(Q1 * (1.f / 16384.f) - mu1 * mu1 + EPSF);
        const float mu2 = S2 * (1.f / 16384.f);
        const float r2  = rsqrtf(Q2 * (1.f / 16384.f) - mu2 * mu2 + EPSF);
        const float gw = __ldg(gnw + tid);
        k1s[tid] = a * gw * r1;
        k2s[tid] = a * gw * r2;
        cpart[tid] = a * (2.f * gbsh[tid] - gw * (mu1 * r1 + mu2 * r2));
    }
    __syncthreads();
    if (tid == 0) {
        float s = 0.f;
        #pragma unroll
        for (int i = 0; i < 16; i++) s += cpart[i];
        Csm = s;
    }
    for (int idx = tid; idx < 2048; idx += 512) {      // fold k into i-side tables
        const int c = idx >> 7, i = idx & 127;
        s1[c * 256 + i] *= k1s[c];
        s2[c * 256 + i] *= k2s[c];
    }
    __syncthreads();

    // ================= C: wts + gate + output (x read once from L2, streamed out) =================
    {
        const int rloc = tid >> 5;                     // 0..15
        const float Cc = Csm;
        #pragma unroll 1
        for (int s = 0; s < 8; s++) {
            const int i = s * 16 + rloc;
            float4 v[16];
            float4 w4 = make_float4(Cc, Cc, Cc, Cc);
            #pragma unroll
            for (int c = 0; c < 16; c++) {
                v[c] = __ldcs((const float4*)(xb + c * HWPX + i * 128) + lane);
                const float a1 = s1[c * 256 + i];
                const float a2 = s2[c * 256 + i];
                const float4 j1 = *(const float4*)(s1 + c * 256 + 128 + 4 * lane);
                const float4 j2 = *(const float4*)(s2 + c * 256 + 128 + 4 * lane);
                w4.x += v[c].x * fmaf(a1, j1.x, a2 * j2.x);
                w4.y += v[c].y * fmaf(a1, j1.y, a2 * j2.y);
                w4.z += v[c].z * fmaf(a1, j1.z, a2 * j2.z);
                w4.w += v[c].w * fmaf(a1, j1.w, a2 * j2.w);
            }
            float4 sw;
            sw.x = siluf(w4.x); sw.y = siluf(w4.y); sw.z = siluf(w4.z); sw.w = siluf(w4.w);
            #pragma unroll
            for (int c = 0; c < 16; c++) {
                float4 o4;
                o4.x = v[c].x * sw.x; o4.y = v[c].y * sw.y;
                o4.z = v[c].z * sw.z; o4.w = v[c].w * sw.w;
                __stcs((float4*)(ob + c * HWPX + i * 128) + lane, o4);
            }
        }
    }
}

// ---------------- launch ----------------
extern "C" void kernel_launch(void* const* d_in, const int* in_sizes, int n_in,
                              void* d_out, int out_size) {
    const float* x    = (const float*)d_in[0];
    const float* w1   = (const float*)d_in[1];
    const float* b1   = (const float*)d_in[2];
    const float* w3   = (const float*)d_in[3];
    const float* b3   = (const float*)d_in[4];
    const float* gn_w = (const float*)d_in[5];
    const float* gn_b = (const float*)d_in[6];
    float* out = (float*)d_out;

    // stage 32768 + s1 4096 + s2 4096 + hwb 4128 + colp 2048 = 47136 floats
    const int smem_bytes = 47136 * (int)sizeof(float);   // 188544 B
    static bool attr_done = false;
    if (!attr_done) {
        cudaFuncSetAttribute(mega, cudaFuncAttributeMaxDynamicSharedMemorySize, smem_bytes);
        attr_done = true;
    }
    mega<<<128, 512, smem_bytes>>>(x, w1, b1, w3, b3, gn_w, gn_b, out);
}

// round 10
// speedup vs baseline: 1.4390x; 1.1420x over previous
#include <cuda_runtime.h>
#include <math.h>
#include <stdint.h>

#define HWPX 16384        // 128*128
#define EPSF 1e-5f

typedef unsigned long long ull;
union V4U { float4 f; ulonglong2 u; };

__device__ __forceinline__ float siluf(float v) { return v / (1.0f + __expf(-v)); }
__device__ __forceinline__ ull pack2(float lo, float hi) {
    ull r; asm("mov.b64 %0, {%1, %2};" : "=l"(r) : "f"(lo), "f"(hi)); return r;
}
__device__ __forceinline__ float2 unpack2(ull v) {
    float2 r; asm("mov.b64 {%0, %1}, %2;" : "=f"(r.x), "=f"(r.y) : "l"(v)); return r;
}
__device__ __forceinline__ ull mul2(ull a, ull b) {
    ull d; asm("mul.rn.f32x2 %0, %1, %2;" : "=l"(d) : "l"(a), "l"(b)); return d;
}
__device__ __forceinline__ ull fma2(ull a, ull b, ull c) {
    ull d; asm("fma.rn.f32x2 %0, %1, %2, %3;" : "=l"(d) : "l"(a), "l"(b), "l"(c)); return d;
}

// One block per bg-group (128 blocks, 512 threads). R6 structure (pipelined LDG
// streaming, full L2 reuse). P2 and C use packed f32x2 math: all accumulators
// stay lane-pair-packed, one horizontal add at the end (pure reassociation).
__global__ __launch_bounds__(512, 1)
void mega(const float* __restrict__ x,
          const float* __restrict__ w1, const float* __restrict__ b1,
          const float* __restrict__ w3, const float* __restrict__ b3,
          const float* __restrict__ gnw, const float* __restrict__ gnb,
          float* __restrict__ out)
{
    extern __shared__ float sm[];
    float* s1  = sm;                       // [16][256]
    float* s2  = sm + 4096;                // [16][256]
    float* hwb = sm + 8192;                // [16][258] means + halo
    ull* hp1  = (ull*)(sm + 12320);        // [16][128] packed (h1,h1);  k-folded before C
    ull* hp2  = (ull*)(sm + 12320 + 4096); // [16][128] packed (h2,h2)
    ull* hq1p = (ull*)(sm + 12320 + 8192); // [16][128] packed (h1^2,h1^2)
    ull* hq2p = (ull*)(sm + 12320 + 12288);// [16][128] packed (h2^2,h2^2)

    __shared__ float w1s[256], w3s[768], b1s[16], b3s[16];
    __shared__ float statv[64], k1s[16], k2s[16], cpart[16], gbsh[16];
    __shared__ float Csm;

    const int bg   = blockIdx.x;
    const int tid  = threadIdx.x;
    const int lane = tid & 31;
    const int wid  = tid >> 5;                   // 0..15 : one warp per channel
    const float* xb = x   + (size_t)bg * 16 * HWPX;
    float*       ob = out + (size_t)bg * 16 * HWPX;

    // ---- stage tiny weights ----
    if (tid < 256) w1s[tid] = __ldg(w1 + tid);
    for (int i2 = tid; i2 < 768; i2 += 512) w3s[i2] = __ldg(w3 + i2 * 3 + 1); // kw=1 column
    if (tid < 16) { b1s[tid] = __ldg(b1 + tid); b3s[tid] = __ldg(b3 + tid); gbsh[tid] = __ldg(gnb + tid); }

    // ================= P1: row means + col means (pipelined, ascending) =================
    {
        const int c = wid;
        const float* g = xb + c * HWPX;
        float* hwc = hwb + c * 258;
        float4 cs = make_float4(0.f, 0.f, 0.f, 0.f);
        float4 va[8], vb[8];

        #pragma unroll
        for (int k = 0; k < 8; k++) va[k] = __ldg((const float4*)(g + k * 128) + lane);

        #pragma unroll 1
        for (int i0 = 0; i0 < 128; i0 += 16) {
            #pragma unroll
            for (int k = 0; k < 8; k++) vb[k] = __ldg((const float4*)(g + (i0 + 8 + k) * 128) + lane);
            {
                float r[8];
                #pragma unroll
                for (int k = 0; k < 8; k++) {
                    cs.x += va[k].x; cs.y += va[k].y; cs.z += va[k].z; cs.w += va[k].w;
                    r[k] = (va[k].x + va[k].y) + (va[k].z + va[k].w);
                }
                #pragma unroll
                for (int off = 16; off; off >>= 1) {
                    #pragma unroll
                    for (int k = 0; k < 8; k++) r[k] += __shfl_down_sync(0xffffffffu, r[k], off);
                }
                if (lane == 0) {
                    #pragma unroll
                    for (int k = 0; k < 8; k++) hwc[1 + i0 + k] = r[k] * (1.f / 128.f);
                }
            }
            if (i0 + 16 < 128) {
                #pragma unroll
                for (int k = 0; k < 8; k++) va[k] = __ldg((const float4*)(g + (i0 + 16 + k) * 128) + lane);
            }
            {
                float r[8];
                #pragma unroll
                for (int k = 0; k < 8; k++) {
                    cs.x += vb[k].x; cs.y += vb[k].y; cs.z += vb[k].z; cs.w += vb[k].w;
                    r[k] = (vb[k].x + vb[k].y) + (vb[k].z + vb[k].w);
                }
                #pragma unroll
                for (int off = 16; off; off >>= 1) {
                    #pragma unroll
                    for (int k = 0; k < 8; k++) r[k] += __shfl_down_sync(0xffffffffu, r[k], off);
                }
                if (lane == 0) {
                    #pragma unroll
                    for (int k = 0; k < 8; k++) hwc[1 + i0 + 8 + k] = r[k] * (1.f / 128.f);
                }
            }
        }
        hwc[129 + 4 * lane + 0] = cs.x * (1.f / 128.f);
        hwc[129 + 4 * lane + 1] = cs.y * (1.f / 128.f);
        hwc[129 + 4 * lane + 2] = cs.z * (1.f / 128.f);
        hwc[129 + 4 * lane + 3] = cs.w * (1.f / 128.f);
        if (lane == 0) { hwc[0] = 0.f; hwc[257] = 0.f; }
    }
    __syncthreads();

    // ================= kA: channel mix over concat length 256 =================
    for (int idx = tid; idx < 4096; idx += 512) {
        const int o = idx >> 8, l = idx & 255;
        float a1 = b1s[o], a2 = b3s[o];
        #pragma unroll
        for (int i = 0; i < 16; i++) {
            const float* h = hwb + i * 258 + l;
            const float h0 = h[0], h1 = h[1], h2 = h[2];
            a1 = fmaf(w1s[o * 16 + i], h1, a1);
            const int wb = (o * 16 + i) * 3;
            a2 = fmaf(w3s[wb], h0, fmaf(w3s[wb + 1], h1, fmaf(w3s[wb + 2], h2, a2)));
        }
        s1[o * 256 + l] = siluf(a1);
        s2[o * 256 + l] = siluf(a2);
    }
    __syncthreads();

    // ---- packed duplicated i-side tables for P2 ----
    for (int idx = tid; idx < 2048; idx += 512) {
        const int c = idx >> 7, i = idx & 127;
        const float a = s1[c * 256 + i];
        const float b = s2[c * 256 + i];
        hp1[idx]  = pack2(a, a);
        hp2[idx]  = pack2(b, b);
        hq1p[idx] = pack2(a * a, a * a);
        hq2p[idx] = pack2(b * b, b * b);
    }
    __syncthreads();

    // ================= P2: packed separable moment sums (pipelined, descending) =================
    {
        const int c = wid;
        const float* g = xb + c * HWPX;
        const float4 wa = *(const float4*)(s1 + c * 256 + 128 + 4 * lane);
        const float4 wb = *(const float4*)(s2 + c * 256 + 128 + 4 * lane);
        const ull waxy = pack2(wa.x, wa.y), wazw = pack2(wa.z, wa.w);
        const ull wbxy = pack2(wb.x, wb.y), wbzw = pack2(wb.z, wb.w);
        const ull wa2xy = mul2(waxy, waxy), wa2zw = mul2(wazw, wazw);
        const ull wb2xy = mul2(wbxy, wbxy), wb2zw = mul2(wbzw, wbzw);

        ull SA = 0ull, QA = 0ull, SB = 0ull, QB = 0ull;   // packed (+0,+0)
        V4U va[8], vb[8];

        #pragma unroll
        for (int k = 0; k < 8; k++) va[k].f = __ldg((const float4*)(g + (120 + k) * 128) + lane);

        #define P2_BODY(BUF, IBASE)                                             \
        {                                                                       \
            _Pragma("unroll")                                                   \
            for (int k = 0; k < 8; k++) {                                       \
                const int i = (IBASE) + k;                                      \
                const ull h1 = hp1[(c << 7) + i];                               \
                const ull h2 = hp2[(c << 7) + i];                               \
                const ull q1 = hq1p[(c << 7) + i];                              \
                const ull q2 = hq2p[(c << 7) + i];                              \
                const ull vxy = BUF[k].u.x, vzw = BUF[k].u.y;                   \
                const ull v2xy = mul2(vxy, vxy), v2zw = mul2(vzw, vzw);         \
                ull d1 = mul2(vxy, waxy); d1 = fma2(vzw, wazw, d1);             \
                ull e1 = mul2(v2xy, wa2xy); e1 = fma2(v2zw, wa2zw, e1);         \
                SA = fma2(h1, d1, SA);                                          \
                QA = fma2(q1, e1, QA);                                          \
                ull d2 = mul2(vxy, wbxy); d2 = fma2(vzw, wbzw, d2);             \
                ull e2 = mul2(v2xy, wb2xy); e2 = fma2(v2zw, wb2zw, e2);         \
                SB = fma2(h2, d2, SB);                                          \
                QB = fma2(q2, e2, QB);                                          \
            }                                                                   \
        }

        #pragma unroll 1
        for (int i0 = 120; i0 >= 0; i0 -= 16) {
            #pragma unroll
            for (int k = 0; k < 8; k++) vb[k].f = __ldg((const float4*)(g + (i0 - 8 + k) * 128) + lane);
            P2_BODY(va, i0)
            if (i0 - 16 >= 0) {
                #pragma unroll
                for (int k = 0; k < 8; k++) va[k].f = __ldg((const float4*)(g + (i0 - 16 + k) * 128) + lane);
            }
            P2_BODY(vb, i0 - 8)
        }
        #undef P2_BODY

        const float2 fa = unpack2(SA), fqa = unpack2(QA);
        const float2 fb = unpack2(SB), fqb = unpack2(QB);
        float sa = fa.x + fa.y, qa = fqa.x + fqa.y;
        float sb = fb.x + fb.y, qb = fqb.x + fqb.y;
        #pragma unroll
        for (int off = 16; off; off >>= 1) {
            sa += __shfl_down_sync(0xffffffffu, sa, off);
            qa += __shfl_down_sync(0xffffffffu, qa, off);
            sb += __shfl_down_sync(0xffffffffu, sb, off);
            qb += __shfl_down_sync(0xffffffffu, qb, off);
        }
        if (lane == 0) { statv[c * 4] = sa; statv[c * 4 + 1] = qa; statv[c * 4 + 2] = sb; statv[c * 4 + 3] = qb; }
    }
    __syncthreads();

    // ================= kB: scalars =================
    if (tid < 16) {
        float m = -1e30f;
        #pragma unroll
        for (int i = 0; i < 16; i++) m = fmaxf(m, gbsh[i]);
        float se = 0.f;
        #pragma unroll
        for (int i = 0; i < 16; i++) se += __expf(gbsh[i] - m);
        const float a = __expf(gbsh[tid] - m) / se;        // a1 == a2 == softmax(gn_b)
        const float S1 = statv[tid * 4], Q1 = statv[tid * 4 + 1];
        const float S2 = statv[tid * 4 + 2], Q2 = statv[tid * 4 + 3];
        const float mu1 = S1 * (1.f / 16384.f);
        const float r1  = rsqrtf(Q1 * (1.f / 16384.f) - mu1 * mu1 + EPSF);
        const float mu2 = S2 * (1.f / 16384.f);
        const float r2  = rsqrtf(Q2 * (1.f / 16384.f) - mu2 * mu2 + EPSF);
        const float gw = __ldg(gnw + tid);
        k1s[tid] = a * gw * r1;
        k2s[tid] = a * gw * r2;
        cpart[tid] = a * (2.f * gbsh[tid] - gw * (mu1 * r1 + mu2 * r2));
    }
    __syncthreads();
    if (tid == 0) {
        float s = 0.f;
        #pragma unroll
        for (int i = 0; i < 16; i++) s += cpart[i];
        Csm = s;
    }
    // fold k1/k2 into the packed i-side tables (j-side stays unscaled)
    for (int idx = tid; idx < 2048; idx += 512) {
        const int c = idx >> 7;
        hp1[idx] = mul2(hp1[idx], pack2(k1s[c], k1s[c]));
        hp2[idx] = mul2(hp2[idx], pack2(k2s[c], k2s[c]));
    }
    __syncthreads();

    // ================= C: packed wts + gate + output (ascending, x read once) =================
    {
        const int rloc = tid >> 5;              // 0..15 rows per sub-iteration
        const float Cc = Csm;
        #pragma unroll 1
        for (int s = 0; s < 8; s++) {
            const int i = s * 16 + rloc;
            V4U v[16];
            ull W1 = pack2(Cc, Cc), W2 = pack2(Cc, Cc);
            #pragma unroll
            for (int c = 0; c < 16; c++) {
                v[c].f = __ldcs((const float4*)(xb + c * HWPX + i * 128) + lane);
                const ull a1 = hp1[(c << 7) + i];          // packed (k1*h1, k1*h1)
                const ull a2 = hp2[(c << 7) + i];
                V4U j1u, j2u;
                j1u.f = *(const float4*)(s1 + c * 256 + 128 + 4 * lane);
                j2u.f = *(const float4*)(s2 + c * 256 + 128 + 4 * lane);
                ull t1 = mul2(a2, j2u.u.x); t1 = fma2(a1, j1u.u.x, t1);
                ull t2 = mul2(a2, j2u.u.y); t2 = fma2(a1, j1u.u.y, t2);
                W1 = fma2(v[c].u.x, t1, W1);
                W2 = fma2(v[c].u.y, t2, W2);
            }
            const float2 wlo = unpack2(W1), whi = unpack2(W2);
            const ull sw1 = pack2(siluf(wlo.x), siluf(wlo.y));
            const ull sw2 = pack2(siluf(whi.x), siluf(whi.y));
            #pragma unroll
            for (int c = 0; c < 16; c++) {
                V4U o;
                o.u.x = mul2(v[c].u.x, sw1);
                o.u.y = mul2(v[c].u.y, sw2);
                __stcs((float4*)(ob + c * HWPX + i * 128) + lane, o.f);
            }
        }
    }
}

// ---------------- launch ----------------
extern "C" void kernel_launch(void* const* d_in, const int* in_sizes, int n_in,
                              void* d_out, int out_size) {
    const float* x    = (const float*)d_in[0];
    const float* w1   = (const float*)d_in[1];
    const float* b1   = (const float*)d_in[2];
    const float* w3   = (const float*)d_in[3];
    const float* b3   = (const float*)d_in[4];
    const float* gn_w = (const float*)d_in[5];
    const float* gn_b = (const float*)d_in[6];
    float* out = (float*)d_out;

    // s1 4096 + s2 4096 + hwb 4128 + packed tables 16384 = 28704 floats
    const int smem_bytes = 28704 * (int)sizeof(float);   // 114816 B
    static bool attr_done = false;
    if (!attr_done) {
        cudaFuncSetAttribute(mega, cudaFuncAttributeMaxDynamicSharedMemorySize, smem_bytes);
        attr_done = true;
    }
    mega<<<128, 512, smem_bytes>>>(x, w1, b1, w3, b3, gn_w, gn_b, out);
}